// round 11
// baseline (speedup 1.0000x reference)
#include <cuda_runtime.h>
#include <math.h>

#define BB 8
#define TT 256
#define DD 512
#define SS 256
#define VV 32000
#define LLAYERS 2

// Scratch (no allocations allowed): 3 x 4MB
__device__ float g_x[BB*TT*DD];     // embedded input
__device__ float g_xin[BB*TT*DD];   // enc pre-activations (x @ enc_W + enc_b)
__device__ float g_hbuf[BB*TT*DD];  // final_pred spikes, then gelu(LN(.)) in place

// ---------------------------------------------------------------------------
// Block-wide (512 threads) pair reduction: sum of a and b across the block.
// Self-contained sync discipline: leading sync protects shm reuse.
// ---------------------------------------------------------------------------
__device__ __forceinline__ void block_red2_512(float &a, float &b, float* shm) {
    #pragma unroll
    for (int off = 16; off > 0; off >>= 1) {
        a += __shfl_xor_sync(0xffffffffu, a, off);
        b += __shfl_xor_sync(0xffffffffu, b, off);
    }
    const int w = threadIdx.x >> 5;
    __syncthreads();
    if ((threadIdx.x & 31) == 0) { shm[w] = a; shm[w + 16] = b; }
    __syncthreads();
    float sa = 0.f, sb = 0.f;
    #pragma unroll
    for (int i = 0; i < 16; i++) { sa += shm[i]; sb += shm[16 + i]; }
    a = sa; b = sb;
}

// ---------------------------------------------------------------------------
// K0: x = tok_emb[ids] + pos_emb[t]
// ---------------------------------------------------------------------------
__global__ __launch_bounds__(256) void embed_kernel(
    const int* __restrict__ ids, const float* __restrict__ tok,
    const float* __restrict__ pos)
{
    int idx = blockIdx.x * 256 + threadIdx.x;      // exactly BB*TT*DD threads
    int r = idx / DD;
    int d = idx - r * DD;
    int t = r & (TT - 1);
    g_x[idx] = tok[ids[r] * DD + d] + pos[t * DD + d];
}

// ---------------------------------------------------------------------------
// K1/K4: C[M,N] = A[M,K] @ B[K,N] + bias[N], fp32, 128x128x8 tiles,
// 256 threads, 8x8 per thread. Requires M%128==0, N%128==0, K%8==0.
// ---------------------------------------------------------------------------
__global__ __launch_bounds__(256) void sgemm_bias_kernel(
    const float* __restrict__ A, const float* __restrict__ Bm,
    const float* __restrict__ bias, float* __restrict__ C,
    int M, int N, int K)
{
    __shared__ float As[8][128];
    __shared__ float Bs[8][128];
    const int tid  = threadIdx.x;
    const int brow = blockIdx.y * 128;
    const int bcol = blockIdx.x * 128;
    const int tx = tid & 15;
    const int ty = tid >> 4;

    const int arow  = tid >> 1;          // 0..127
    const int acol4 = (tid & 1) * 4;     // 0 or 4
    const int bkrow = tid >> 5;          // 0..7
    const int bcol4 = (tid & 31) * 4;    // 0..124

    float acc[8][8];
    #pragma unroll
    for (int i = 0; i < 8; i++)
        #pragma unroll
        for (int j = 0; j < 8; j++) acc[i][j] = 0.f;

    for (int k0 = 0; k0 < K; k0 += 8) {
        float4 av = *(const float4*)(A + (size_t)(brow + arow) * K + k0 + acol4);
        float4 bv = *(const float4*)(Bm + (size_t)(k0 + bkrow) * N + bcol + bcol4);
        __syncthreads();
        As[acol4 + 0][arow] = av.x;
        As[acol4 + 1][arow] = av.y;
        As[acol4 + 2][arow] = av.z;
        As[acol4 + 3][arow] = av.w;
        *(float4*)(&Bs[bkrow][bcol4]) = bv;
        __syncthreads();
        #pragma unroll
        for (int kk = 0; kk < 8; kk++) {
            float a[8], bb[8];
            *(float4*)(a)      = *(const float4*)(&As[kk][ty * 4]);
            *(float4*)(a + 4)  = *(const float4*)(&As[kk][64 + ty * 4]);
            *(float4*)(bb)     = *(const float4*)(&Bs[kk][tx * 4]);
            *(float4*)(bb + 4) = *(const float4*)(&Bs[kk][64 + tx * 4]);
            #pragma unroll
            for (int i = 0; i < 8; i++)
                #pragma unroll
                for (int j = 0; j < 8; j++)
                    acc[i][j] = fmaf(a[i], bb[j], acc[i][j]);
        }
    }

    #pragma unroll
    for (int i = 0; i < 8; i++) {
        int lr = (i < 4) ? (ty * 4 + i) : (64 + ty * 4 + (i - 4));
        int r  = brow + lr;
        #pragma unroll
        for (int jj = 0; jj < 2; jj++) {
            int c = bcol + jj * 64 + tx * 4;
            float4 o;
            o.x = acc[i][jj * 4 + 0] + bias[c + 0];
            o.y = acc[i][jj * 4 + 1] + bias[c + 1];
            o.z = acc[i][jj * 4 + 2] + bias[c + 2];
            o.w = acc[i][jj * 4 + 3] + bias[c + 3];
            *(float4*)(C + (size_t)r * N + c) = o;
        }
    }
}

// ---------------------------------------------------------------------------
// K2: the recurrent scan. One CTA (512 threads) per batch element.
// All state lives in registers/shared; weights stream from L2.
// ---------------------------------------------------------------------------
__global__ __launch_bounds__(512, 1) void scan_kernel(
    const float* __restrict__ enc_tau, const float* __restrict__ enc_thr,
    const float* __restrict__ gen_W,  const float* __restrict__ gen_b,
    const float* __restrict__ gen_tau,const float* __restrict__ gen_thr,
    const float* __restrict__ inf_W,  const float* __restrict__ inf_b,
    const float* __restrict__ inf_tau,const float* __restrict__ inf_thr,
    const float* __restrict__ ne_g,   const float* __restrict__ ne_b,
    const float* __restrict__ ns_g,   const float* __restrict__ ns_b)
{
    __shared__ float shStates[LLAYERS][SS];
    __shared__ float shErr[DD];
    __shared__ float shPart[DD];
    __shared__ float shRed[32];

    const int tid = threadIdx.x;           // owns feature d = tid (D side)
    const int b   = blockIdx.x;
    const int s_  = tid & (SS - 1);        // S-side index (threads < 256 own it)
    const int hf  = tid >> 8;              // input-half for inf GEMV

    // Per-thread constant parameters (D side)
    float encDecay = expf(-1.0f / fmaxf(enc_tau[tid], 1.0f));
    float encThrR  = enc_thr[tid];
    float genB[2], genDec[2], genThr[2], neG[2], neB[2];
    #pragma unroll
    for (int j = 0; j < 2; j++) {
        genB[j]   = gen_b[j * DD + tid];
        genDec[j] = expf(-1.0f / fmaxf(gen_tau[j * DD + tid], 1.0f));
        genThr[j] = gen_thr[j * DD + tid];
        neG[j]    = ne_g[j * DD + tid];
        neB[j]    = ne_b[j * DD + tid];
    }
    // S-side parameters (only threads < 256 use them)
    float infB[2] = {0.f, 0.f}, infDec[2] = {1.f, 1.f}, infThr[2] = {0.f, 0.f};
    float nsG[2] = {0.f, 0.f}, nsB[2] = {0.f, 0.f};
    if (tid < SS) {
        #pragma unroll
        for (int j = 0; j < 2; j++) {
            infB[j]   = inf_b[j * SS + tid];
            infDec[j] = expf(-1.0f / fmaxf(inf_tau[j * SS + tid], 1.0f));
            infThr[j] = inf_thr[j * SS + tid];
            nsG[j]    = ns_g[j * SS + tid];
            nsB[j]    = ns_b[j * SS + tid];
        }
        shStates[0][tid] = 0.f;
        shStates[1][tid] = 0.f;
    }
    float mem_enc = 0.f;
    float gmem[2] = {0.f, 0.f};
    float imem[2] = {0.f, 0.f};
    __syncthreads();

    for (int t = 0; t < TT; t++) {
        // ---- input encoder LIF (pre-activation precomputed in g_xin) ----
        float xin = g_xin[(size_t)(b * TT + t) * DD + tid];
        float m  = mem_enc * encDecay + xin;
        float sp = (m >= encThrR) ? 1.f : 0.f;
        mem_enc  = m - m * sp;
        float bu = sp;

        // ---- hierarchical layers ----
        #pragma unroll
        for (int j = 0; j < LLAYERS; j++) {
            // generative GEMV: pred[d] = LIF(states[j] @ gen_W[j] + gen_b[j])
            const float* W = gen_W + j * SS * DD + tid;
            float acc = genB[j];
            #pragma unroll 8
            for (int s0 = 0; s0 < SS; s0++)
                acc = fmaf(shStates[j][s0], W[s0 * DD], acc);
            float mg  = gmem[j] * genDec[j] + acc;
            float spg = (mg >= genThr[j]) ? 1.f : 0.f;
            gmem[j] = mg - mg * spg;

            // err = LayerNorm(bu - pred)
            float dv = bu - spg;
            float sa = dv, sb = dv * dv;
            block_red2_512(sa, sb, shRed);
            float mu   = sa * (1.f / DD);
            float rstd = rsqrtf(sb * (1.f / DD) - mu * mu + 1e-5f);
            float e = (dv - mu) * rstd * neG[j] + neB[j];
            shErr[tid] = e;
            bu = e;
            __syncthreads();

            // inference GEMV: su = LIF(err @ inf_W[j] + inf_b[j]); split input 2-way
            {
                const float* Wi = inf_W + j * DD * SS + (hf * 256) * SS + s_;
                const float* ep = shErr + hf * 256;
                float a2 = 0.f;
                #pragma unroll 8
                for (int d0 = 0; d0 < 256; d0++)
                    a2 = fmaf(ep[d0], Wi[d0 * SS], a2);
                shPart[tid] = a2;
            }
            __syncthreads();
            float pre = 0.f;
            if (tid < SS) {
                float tot = shPart[tid] + shPart[tid + 256] + infB[j];
                float mi  = imem[j] * infDec[j] + tot;
                float spi = (mi >= infThr[j]) ? 1.f : 0.f;
                imem[j] = mi - mi * spi;
                pre = shStates[j][tid] + spi;
            }
            // states[j] = LayerNorm(states[j] + su) over S (pad with zeros)
            float sa2 = pre, sb2 = pre * pre;
            block_red2_512(sa2, sb2, shRed);
            float mu2   = sa2 * (1.f / SS);
            float rstd2 = rsqrtf(sb2 * (1.f / SS) - mu2 * mu2 + 1e-5f);
            if (tid < SS)
                shStates[j][tid] = (pre - mu2) * rstd2 * nsG[j] + nsB[j];
            __syncthreads();
        }

        // ---- extra decode on last layer ----
        {
            const float* W = gen_W + 1 * SS * DD + tid;
            float acc = genB[1];
            #pragma unroll 8
            for (int s0 = 0; s0 < SS; s0++)
                acc = fmaf(shStates[1][s0], W[s0 * DD], acc);
            float mg  = gmem[1] * genDec[1] + acc;
            float spg = (mg >= genThr[1]) ? 1.f : 0.f;
            gmem[1] = mg - mg * spg;
            g_hbuf[(size_t)(b * TT + t) * DD + tid] = spg;   // final_pred

            float dv = -spg;
            float sa = dv, sb = dv * dv;
            block_red2_512(sa, sb, shRed);
            float mu   = sa * (1.f / DD);
            float rstd = rsqrtf(sb * (1.f / DD) - mu * mu + 1e-5f);
            float e = (dv - mu) * rstd * neG[1] + neB[1];
            shErr[tid] = e;
            __syncthreads();

            const float* Wi = inf_W + 1 * DD * SS + (hf * 256) * SS + s_;
            const float* ep = shErr + hf * 256;
            float a2 = 0.f;
            #pragma unroll 8
            for (int d0 = 0; d0 < 256; d0++)
                a2 = fmaf(ep[d0], Wi[d0 * SS], a2);
            shPart[tid] = a2;
            __syncthreads();
            if (tid < SS) {
                float tot = shPart[tid] + shPart[tid + 256] + infB[1];
                float mi  = imem[1] * infDec[1] + tot;
                float spi = (mi >= infThr[1]) ? 1.f : 0.f;
                imem[1] = mi - mi * spi;   // membranes advance; spikes discarded
            }
            // next iteration's first shared write is inside block_red2 (leading sync)
        }
    }
}

// ---------------------------------------------------------------------------
// K3: h = gelu(LayerNorm(preds) * out_g + out_b), exact gelu, in place.
// One CTA per (b,t) row.
// ---------------------------------------------------------------------------
__global__ __launch_bounds__(512) void h_kernel(
    const float* __restrict__ gvec, const float* __restrict__ bvec)
{
    __shared__ float shRed[32];
    const int r   = blockIdx.x;
    const int tid = threadIdx.x;
    float x = g_hbuf[(size_t)r * DD + tid];
    float sa = x, sb = x * x;
    block_red2_512(sa, sb, shRed);
    float mu   = sa * (1.f / DD);
    float rstd = rsqrtf(sb * (1.f / DD) - mu * mu + 1e-5f);
    float y = (x - mu) * rstd * gvec[tid] + bvec[tid];
    float ge = 0.5f * y * (1.0f + erff(y * 0.70710678118654752440f));
    g_hbuf[(size_t)r * DD + tid] = ge;
}

// ---------------------------------------------------------------------------
extern "C" void kernel_launch(void* const* d_in, const int* in_sizes, int n_in,
                              void* d_out, int out_size)
{
    const int*   ids     = (const int*)  d_in[0];
    const float* tok     = (const float*)d_in[1];
    const float* pos     = (const float*)d_in[2];
    const float* enc_W   = (const float*)d_in[3];
    const float* enc_b   = (const float*)d_in[4];
    const float* enc_tau = (const float*)d_in[5];
    const float* enc_thr = (const float*)d_in[6];
    const float* gen_W   = (const float*)d_in[7];
    const float* gen_b   = (const float*)d_in[8];
    const float* gen_tau = (const float*)d_in[9];
    const float* gen_thr = (const float*)d_in[10];
    const float* inf_W   = (const float*)d_in[11];
    const float* inf_b   = (const float*)d_in[12];
    const float* inf_tau = (const float*)d_in[13];
    const float* inf_thr = (const float*)d_in[14];
    const float* ne_g    = (const float*)d_in[15];
    const float* ne_b    = (const float*)d_in[16];
    const float* ns_g    = (const float*)d_in[17];
    const float* ns_b    = (const float*)d_in[18];
    const float* out_g   = (const float*)d_in[19];
    const float* out_b   = (const float*)d_in[20];
    const float* out_W   = (const float*)d_in[21];
    const float* out_b2  = (const float*)d_in[22];
    float* out = (float*)d_out;

    float *px, *pxin, *ph;
    cudaGetSymbolAddress((void**)&px,   g_x);
    cudaGetSymbolAddress((void**)&pxin, g_xin);
    cudaGetSymbolAddress((void**)&ph,   g_hbuf);

    // K0: embedding
    embed_kernel<<<(BB * TT * DD) / 256, 256>>>(ids, tok, pos);

    // K1: enc pre-activations for ALL timesteps (hoisted out of the scan)
    {
        dim3 grid(DD / 128, (BB * TT) / 128);
        sgemm_bias_kernel<<<grid, 256>>>(px, enc_W, enc_b, pxin, BB * TT, DD, DD);
    }

    // K2: recurrent scan, one CTA per batch
    scan_kernel<<<BB, 512>>>(enc_tau, enc_thr, gen_W, gen_b, gen_tau, gen_thr,
                             inf_W, inf_b, inf_tau, inf_thr,
                             ne_g, ne_b, ns_g, ns_b);

    // K3: LN + exact GELU epilogue on preds
    h_kernel<<<BB * TT, 512>>>(out_g, out_b);

    // K4: logits = h @ out_W + out_b2
    {
        dim3 grid(VV / 128, (BB * TT) / 128);
        sgemm_bias_kernel<<<grid, 256>>>(ph, out_W, out_b2, out, BB * TT, VV, DD);
    }
}

// round 14
// speedup vs baseline: 3.2306x; 3.2306x over previous
#include <cuda_runtime.h>
#include <math.h>

#define BB 8
#define TT 256
#define DD 512
#define SS 256
#define VV 32000
#define CL 8            // CTAs per cluster (one cluster per batch element)

// Scratch (no allocations allowed)
__device__ float g_x[BB*TT*DD];      // embedded input
__device__ float g_xin[BB*TT*DD];    // enc pre-activations
__device__ float g_hbuf[BB*TT*DD];   // final_pred spikes -> gelu(LN(.))
__device__ float g_dv[3][BB*DD];     // raw pre-LN error vectors (j0, j1, extra)
__device__ float g_pre[2][BB*SS];    // raw pre-LN state vectors (j0, j1)

// ---------------------------------------------------------------------------
// Block-wide (512 threads) pair reduction. Leading sync protects shm reuse.
// ---------------------------------------------------------------------------
__device__ __forceinline__ void block_red2_512(float &a, float &b, float* shm) {
    #pragma unroll
    for (int off = 16; off > 0; off >>= 1) {
        a += __shfl_xor_sync(0xffffffffu, a, off);
        b += __shfl_xor_sync(0xffffffffu, b, off);
    }
    const int w = threadIdx.x >> 5;
    __syncthreads();
    if ((threadIdx.x & 31) == 0) { shm[w] = a; shm[w + 16] = b; }
    __syncthreads();
    float sa = 0.f, sb = 0.f;
    #pragma unroll
    for (int i = 0; i < 16; i++) { sa += shm[i]; sb += shm[16 + i]; }
    a = sa; b = sb;
}

__device__ __forceinline__ void cluster_sync() {
    asm volatile("barrier.cluster.arrive.aligned;" ::: "memory");
    asm volatile("barrier.cluster.wait.aligned;" ::: "memory");
}

// ---------------------------------------------------------------------------
// K0: x = tok_emb[ids] + pos_emb[t]
// ---------------------------------------------------------------------------
__global__ __launch_bounds__(256) void embed_kernel(
    const int* __restrict__ ids, const float* __restrict__ tok,
    const float* __restrict__ pos)
{
    int idx = blockIdx.x * 256 + threadIdx.x;
    int r = idx / DD;
    int d = idx - r * DD;
    int t = r & (TT - 1);
    g_x[idx] = tok[ids[r] * DD + d] + pos[t * DD + d];
}

// ---------------------------------------------------------------------------
// K1/K4: C[M,N] = A[M,K] @ B[K,N] + bias[N], fp32, 128x128x8 tiles.
// ---------------------------------------------------------------------------
__global__ __launch_bounds__(256) void sgemm_bias_kernel(
    const float* __restrict__ A, const float* __restrict__ Bm,
    const float* __restrict__ bias, float* __restrict__ C,
    int M, int N, int K)
{
    __shared__ float As[8][128];
    __shared__ float Bs[8][128];
    const int tid  = threadIdx.x;
    const int brow = blockIdx.y * 128;
    const int bcol = blockIdx.x * 128;
    const int tx = tid & 15;
    const int ty = tid >> 4;

    const int arow  = tid >> 1;
    const int acol4 = (tid & 1) * 4;
    const int bkrow = tid >> 5;
    const int bcol4 = (tid & 31) * 4;

    float acc[8][8];
    #pragma unroll
    for (int i = 0; i < 8; i++)
        #pragma unroll
        for (int j = 0; j < 8; j++) acc[i][j] = 0.f;

    for (int k0 = 0; k0 < K; k0 += 8) {
        float4 av = *(const float4*)(A + (size_t)(brow + arow) * K + k0 + acol4);
        float4 bv = *(const float4*)(Bm + (size_t)(k0 + bkrow) * N + bcol + bcol4);
        __syncthreads();
        As[acol4 + 0][arow] = av.x;
        As[acol4 + 1][arow] = av.y;
        As[acol4 + 2][arow] = av.z;
        As[acol4 + 3][arow] = av.w;
        *(float4*)(&Bs[bkrow][bcol4]) = bv;
        __syncthreads();
        #pragma unroll
        for (int kk = 0; kk < 8; kk++) {
            float a[8], bb[8];
            *(float4*)(a)      = *(const float4*)(&As[kk][ty * 4]);
            *(float4*)(a + 4)  = *(const float4*)(&As[kk][64 + ty * 4]);
            *(float4*)(bb)     = *(const float4*)(&Bs[kk][tx * 4]);
            *(float4*)(bb + 4) = *(const float4*)(&Bs[kk][64 + tx * 4]);
            #pragma unroll
            for (int i = 0; i < 8; i++)
                #pragma unroll
                for (int j = 0; j < 8; j++)
                    acc[i][j] = fmaf(a[i], bb[j], acc[i][j]);
        }
    }

    #pragma unroll
    for (int i = 0; i < 8; i++) {
        int lr = (i < 4) ? (ty * 4 + i) : (64 + ty * 4 + (i - 4));
        int r  = brow + lr;
        #pragma unroll
        for (int jj = 0; jj < 2; jj++) {
            int c = bcol + jj * 64 + tx * 4;
            float4 o;
            o.x = acc[i][jj * 4 + 0] + bias[c + 0];
            o.y = acc[i][jj * 4 + 1] + bias[c + 1];
            o.z = acc[i][jj * 4 + 2] + bias[c + 2];
            o.w = acc[i][jj * 4 + 3] + bias[c + 3];
            *(float4*)(C + (size_t)r * N + c) = o;
        }
    }
}

// ---------------------------------------------------------------------------
// K2: recurrent scan. One 8-CTA cluster per batch; CTA rank r owns
// D-rows [r*64, r*64+64) and S-rows [r*32, r*32+32). 512 threads/CTA.
// Cross-CTA exchange of raw pre-LN vectors via L2 (__stcg/__ldcg) ordered by
// cluster barriers; LN statistics recomputed redundantly (bitwise identical)
// in every CTA so each LN+broadcast costs exactly ONE cluster sync.
// ---------------------------------------------------------------------------
__global__ __launch_bounds__(512, 1) __cluster_dims__(CL, 1, 1)
void scan_kernel(
    const float* __restrict__ enc_tau, const float* __restrict__ enc_thr,
    const float* __restrict__ gen_W,  const float* __restrict__ gen_b,
    const float* __restrict__ gen_tau,const float* __restrict__ gen_thr,
    const float* __restrict__ inf_W,  const float* __restrict__ inf_b,
    const float* __restrict__ inf_tau,const float* __restrict__ inf_thr,
    const float* __restrict__ ne_g,   const float* __restrict__ ne_b,
    const float* __restrict__ ns_g,   const float* __restrict__ ns_b)
{
    __shared__ float shState[2][SS];
    __shared__ float shErr[DD];
    __shared__ float shPart[512];
    __shared__ float shRed[32];

    const int tid = threadIdx.x;
    const int r   = blockIdx.x;            // cluster rank 0..7
    const int b   = blockIdx.y;            // batch
    const int dO  = r * 64 + (tid & 63);   // gen-GEMV output row
    const int sO  = r * 32 + (tid & 31);   // inf-GEMV output row
    const int kcg = tid >> 6;              // gen K-chunk 0..7 (32 inputs each)
    const int kci = tid >> 5;              // inf K-chunk 0..15 (32 inputs each)

    // err-LN params: thread tid owns d = tid (full D, redundant per CTA)
    float neGv[2], neBv[2];
    #pragma unroll
    for (int j = 0; j < 2; j++) { neGv[j] = ne_g[j*DD + tid]; neBv[j] = ne_b[j*DD + tid]; }
    // state-LN params: thread tid<SS owns s = tid
    float nsGv[2] = {0.f, 0.f}, nsBv[2] = {0.f, 0.f};
    if (tid < SS) {
        #pragma unroll
        for (int j = 0; j < 2; j++) { nsGv[j] = ns_g[j*SS + tid]; nsBv[j] = ns_b[j*SS + tid]; }
        shState[0][tid] = 0.f;
        shState[1][tid] = 0.f;
    }
    // own D-row params (tid<64 owns d = r*64+tid)
    float encDec = 0.f, encThrv = 0.f;
    float genBv[2] = {0.f,0.f}, genDecv[2] = {1.f,1.f}, genThrv[2] = {0.f,0.f};
    float mem_enc = 0.f, gmem[2] = {0.f, 0.f};
    if (tid < 64) {
        int d = r * 64 + tid;
        encDec  = expf(-1.0f / fmaxf(enc_tau[d], 1.0f));
        encThrv = enc_thr[d];
        #pragma unroll
        for (int j = 0; j < 2; j++) {
            genBv[j]   = gen_b[j*DD + d];
            genDecv[j] = expf(-1.0f / fmaxf(gen_tau[j*DD + d], 1.0f));
            genThrv[j] = gen_thr[j*DD + d];
        }
    }
    // own S-row params (tid<32 owns s = r*32+tid)
    float infBv[2] = {0.f,0.f}, infDecv[2] = {1.f,1.f}, infThrv[2] = {0.f,0.f};
    float imem[2] = {0.f, 0.f};
    if (tid < 32) {
        int s = r * 32 + tid;
        #pragma unroll
        for (int j = 0; j < 2; j++) {
            infBv[j]   = inf_b[j*SS + s];
            infDecv[j] = expf(-1.0f / fmaxf(inf_tau[j*SS + s], 1.0f));
            infThrv[j] = inf_thr[j*SS + s];
        }
    }
    __syncthreads();

    float* dvb[3] = { g_dv[0] + b*DD, g_dv[1] + b*DD, g_dv[2] + b*DD };
    float* prb[2] = { g_pre[0] + b*SS, g_pre[1] + b*SS };

    float bu = 0.f;

    for (int t = 0; t < TT; t++) {
        // ---- input encoder LIF ----
        if (tid < 64) {
            float xin = g_xin[(size_t)(b*TT + t) * DD + r*64 + tid];
            float m  = mem_enc * encDec + xin;
            float sp = (m >= encThrv) ? 1.f : 0.f;
            mem_enc  = m - m * sp;
            bu = sp;
        }

        #pragma unroll
        for (int j = 0; j < 2; j++) {
            // ---- generative GEMV (64 outputs/CTA, 8-way K-split) ----
            {
                const float* Wp = gen_W + (size_t)j*SS*DD + (size_t)(kcg*32)*DD + dO;
                const float* sv = &shState[j][kcg * 32];
                float a0=0.f, a1=0.f, a2=0.f, a3=0.f;
                #pragma unroll
                for (int q = 0; q < 32; q += 4) {
                    a0 = fmaf(sv[q+0], Wp[(q+0)*DD], a0);
                    a1 = fmaf(sv[q+1], Wp[(q+1)*DD], a1);
                    a2 = fmaf(sv[q+2], Wp[(q+2)*DD], a2);
                    a3 = fmaf(sv[q+3], Wp[(q+3)*DD], a3);
                }
                __syncthreads();
                shPart[tid] = (a0 + a1) + (a2 + a3);
                __syncthreads();
            }
            if (tid < 64) {
                float acc = genBv[j];
                #pragma unroll
                for (int k2 = 0; k2 < 8; k2++) acc += shPart[tid + 64*k2];
                float mg  = gmem[j] * genDecv[j] + acc;
                float spg = (mg >= genThrv[j]) ? 1.f : 0.f;
                gmem[j] = mg - mg * spg;
                __stcg(dvb[j] + r*64 + tid, bu - spg);     // raw dv slice
            }
            cluster_sync();
            // ---- err = LN(dv) over D, recomputed redundantly everywhere ----
            {
                float v  = __ldcg(dvb[j] + tid);
                float sa = v, sb = v * v;
                block_red2_512(sa, sb, shRed);
                float mu   = sa * (1.f / DD);
                float rstd = rsqrtf(sb * (1.f / DD) - mu*mu + 1e-5f);
                shErr[tid] = (v - mu) * rstd * neGv[j] + neBv[j];
                __syncthreads();
                if (tid < 64) bu = shErr[r*64 + tid];
            }
            // ---- inference GEMV (32 outputs/CTA, 16-way K-split) ----
            {
                const float* Wi = inf_W + (size_t)j*DD*SS + (size_t)(kci*32)*SS + sO;
                const float* ev = &shErr[kci * 32];
                float a0=0.f, a1=0.f, a2=0.f, a3=0.f;
                #pragma unroll
                for (int q = 0; q < 32; q += 4) {
                    a0 = fmaf(ev[q+0], Wi[(q+0)*SS], a0);
                    a1 = fmaf(ev[q+1], Wi[(q+1)*SS], a1);
                    a2 = fmaf(ev[q+2], Wi[(q+2)*SS], a2);
                    a3 = fmaf(ev[q+3], Wi[(q+3)*SS], a3);
                }
                __syncthreads();
                shPart[tid] = (a0 + a1) + (a2 + a3);
                __syncthreads();
            }
            if (tid < 32) {
                float tot = infBv[j];
                #pragma unroll
                for (int k2 = 0; k2 < 16; k2++) tot += shPart[tid + 32*k2];
                float mi  = imem[j] * infDecv[j] + tot;
                float spi = (mi >= infThrv[j]) ? 1.f : 0.f;
                imem[j] = mi - mi * spi;
                __stcg(prb[j] + r*32 + tid, shState[j][r*32 + tid] + spi);  // raw pre
            }
            cluster_sync();
            // ---- states[j] = LN(pre) over S, redundant ----
            {
                float pv = (tid < SS) ? __ldcg(prb[j] + tid) : 0.f;
                float sa = pv, sb = pv * pv;
                block_red2_512(sa, sb, shRed);
                float mu   = sa * (1.f / SS);
                float rstd = rsqrtf(sb * (1.f / SS) - mu*mu + 1e-5f);
                if (tid < SS) shState[j][tid] = (pv - mu) * rstd * nsGv[j] + nsBv[j];
                __syncthreads();
            }
        }

        // ---- extra decode on last layer ----
        {
            const float* Wp = gen_W + (size_t)1*SS*DD + (size_t)(kcg*32)*DD + dO;
            const float* sv = &shState[1][kcg * 32];
            float a0=0.f, a1=0.f, a2=0.f, a3=0.f;
            #pragma unroll
            for (int q = 0; q < 32; q += 4) {
                a0 = fmaf(sv[q+0], Wp[(q+0)*DD], a0);
                a1 = fmaf(sv[q+1], Wp[(q+1)*DD], a1);
                a2 = fmaf(sv[q+2], Wp[(q+2)*DD], a2);
                a3 = fmaf(sv[q+3], Wp[(q+3)*DD], a3);
            }
            __syncthreads();
            shPart[tid] = (a0 + a1) + (a2 + a3);
            __syncthreads();
        }
        if (tid < 64) {
            float acc = genBv[1];
            #pragma unroll
            for (int k2 = 0; k2 < 8; k2++) acc += shPart[tid + 64*k2];
            float mg  = gmem[1] * genDecv[1] + acc;
            float spg = (mg >= genThrv[1]) ? 1.f : 0.f;
            gmem[1] = mg - mg * spg;
            g_hbuf[(size_t)(b*TT + t) * DD + r*64 + tid] = spg;  // final_pred
            __stcg(dvb[2] + r*64 + tid, -spg);
        }
        cluster_sync();
        {
            float v  = __ldcg(dvb[2] + tid);
            float sa = v, sb = v * v;
            block_red2_512(sa, sb, shRed);
            float mu   = sa * (1.f / DD);
            float rstd = rsqrtf(sb * (1.f / DD) - mu*mu + 1e-5f);
            shErr[tid] = (v - mu) * rstd * neGv[1] + neBv[1];
            __syncthreads();
        }
        {
            const float* Wi = inf_W + (size_t)1*DD*SS + (size_t)(kci*32)*SS + sO;
            const float* ev = &shErr[kci * 32];
            float a0=0.f, a1=0.f, a2=0.f, a3=0.f;
            #pragma unroll
            for (int q = 0; q < 32; q += 4) {
                a0 = fmaf(ev[q+0], Wi[(q+0)*SS], a0);
                a1 = fmaf(ev[q+1], Wi[(q+1)*SS], a1);
                a2 = fmaf(ev[q+2], Wi[(q+2)*SS], a2);
                a3 = fmaf(ev[q+3], Wi[(q+3)*SS], a3);
            }
            __syncthreads();
            shPart[tid] = (a0 + a1) + (a2 + a3);
            __syncthreads();
        }
        if (tid < 32) {
            float tot = infBv[1];
            #pragma unroll
            for (int k2 = 0; k2 < 16; k2++) tot += shPart[tid + 32*k2];
            float mi  = imem[1] * infDecv[1] + tot;
            float spi = (mi >= infThrv[1]) ? 1.f : 0.f;
            imem[1] = mi - mi * spi;        // membranes advance; spikes discarded
        }
        // next iteration's gen GEMV has a leading __syncthreads before shPart write
    }
}

// ---------------------------------------------------------------------------
// K3: h = gelu(LayerNorm(preds) * out_g + out_b), exact gelu, in place.
// ---------------------------------------------------------------------------
__global__ __launch_bounds__(512) void h_kernel(
    const float* __restrict__ gvec, const float* __restrict__ bvec)
{
    __shared__ float shRed[32];
    const int r   = blockIdx.x;
    const int tid = threadIdx.x;
    float x = g_hbuf[(size_t)r * DD + tid];
    float sa = x, sb = x * x;
    block_red2_512(sa, sb, shRed);
    float mu   = sa * (1.f / DD);
    float rstd = rsqrtf(sb * (1.f / DD) - mu * mu + 1e-5f);
    float y = (x - mu) * rstd * gvec[tid] + bvec[tid];
    float ge = 0.5f * y * (1.0f + erff(y * 0.70710678118654752440f));
    g_hbuf[(size_t)r * DD + tid] = ge;
}

// ---------------------------------------------------------------------------
extern "C" void kernel_launch(void* const* d_in, const int* in_sizes, int n_in,
                              void* d_out, int out_size)
{
    const int*   ids     = (const int*)  d_in[0];
    const float* tok     = (const float*)d_in[1];
    const float* pos     = (const float*)d_in[2];
    const float* enc_W   = (const float*)d_in[3];
    const float* enc_b   = (const float*)d_in[4];
    const float* enc_tau = (const float*)d_in[5];
    const float* enc_thr = (const float*)d_in[6];
    const float* gen_W   = (const float*)d_in[7];
    const float* gen_b   = (const float*)d_in[8];
    const float* gen_tau = (const float*)d_in[9];
    const float* gen_thr = (const float*)d_in[10];
    const float* inf_W   = (const float*)d_in[11];
    const float* inf_b   = (const float*)d_in[12];
    const float* inf_tau = (const float*)d_in[13];
    const float* inf_thr = (const float*)d_in[14];
    const float* ne_g    = (const float*)d_in[15];
    const float* ne_b    = (const float*)d_in[16];
    const float* ns_g    = (const float*)d_in[17];
    const float* ns_b    = (const float*)d_in[18];
    const float* out_g   = (const float*)d_in[19];
    const float* out_b   = (const float*)d_in[20];
    const float* out_W   = (const float*)d_in[21];
    const float* out_b2  = (const float*)d_in[22];
    float* out = (float*)d_out;

    float *px, *pxin, *ph;
    cudaGetSymbolAddress((void**)&px,   g_x);
    cudaGetSymbolAddress((void**)&pxin, g_xin);
    cudaGetSymbolAddress((void**)&ph,   g_hbuf);

    // K0: embedding
    embed_kernel<<<(BB * TT * DD) / 256, 256>>>(ids, tok, pos);

    // K1: enc pre-activations for ALL timesteps (hoisted out of the scan)
    {
        dim3 grid(DD / 128, (BB * TT) / 128);
        sgemm_bias_kernel<<<grid, 256>>>(px, enc_W, enc_b, pxin, BB * TT, DD, DD);
    }

    // K2: recurrent scan — one 8-CTA cluster per batch (64 CTAs total)
    {
        dim3 grid(CL, BB);
        scan_kernel<<<grid, 512>>>(enc_tau, enc_thr, gen_W, gen_b, gen_tau, gen_thr,
                                   inf_W, inf_b, inf_tau, inf_thr,
                                   ne_g, ne_b, ns_g, ns_b);
    }

    // K3: LN + exact GELU epilogue on preds
    h_kernel<<<BB * TT, 512>>>(out_g, out_b);

    // K4: logits = h @ out_W + out_b2
    {
        dim3 grid(VV / 128, (BB * TT) / 128);
        sgemm_bias_kernel<<<grid, 256>>>(ph, out_W, out_b2, out, BB * TT, VV, DD);
    }
}